// round 13
// baseline (speedup 1.0000x reference)
#include <cuda_runtime.h>
#include <cuda_bf16.h>
#include <cstdint>

// Problem constants (fixed by the dataset)
#define NN 50000
#define EE 800000
#define IN_F 512
#define HID_F 256
#define LAT_F 128

// ---------------- scratch (static device globals; no runtime alloc) ----------
__device__ __align__(16) float g_m1[NN * HID_F];    // x @ W1
__device__ __align__(16) float g_agg1[NN * HID_F];  // layer-1 aggregate (pre-activation)
__device__ __align__(16) float g_agg2[NN * HID_F];  // layer-2 aggregate
__device__ float g_dis[NN];                         // rsqrt(deg)
__device__ float g_deg[NN];                         // weighted degree accum
__device__ int   g_cnt[NN];                         // incoming-edge count
__device__ int   g_rowptr[NN + 1];                  // CSR row pointers
__device__ int   g_fill[NN];                        // scan temp / fill cursors
__device__ int   g_part[256];                       // scan block partials
__device__ int   g_col[EE];                         // CSR: src per edge (sorted by dst)
__device__ float g_val[EE];                         // CSR: precomputed norm per edge
__device__ int   g_is64;                            // edge_index dtype flag

// Pre-transposed, bf16 hi/lo split weights: [N, K] K-major (= B col-major for mma)
__device__ __align__(16) __nv_bfloat16 g_W1T_hi[HID_F * IN_F];
__device__ __align__(16) __nv_bfloat16 g_W1T_lo[HID_F * IN_F];
__device__ __align__(16) __nv_bfloat16 g_W2T_hi[HID_F * HID_F];  // [256 (mu|lv), 256]
__device__ __align__(16) __nv_bfloat16 g_W2T_lo[HID_F * HID_F];

// ---------------- warp mma (Ampere-era PTX; no arch-feature gating) ----------
__device__ __forceinline__ void mma_bf16(float* c, const uint32_t* a, const uint32_t* b) {
    asm volatile(
        "mma.sync.aligned.m16n8k16.row.col.f32.bf16.bf16.f32 "
        "{%0,%1,%2,%3}, {%4,%5,%6,%7}, {%8,%9}, {%0,%1,%2,%3};"
        : "+f"(c[0]), "+f"(c[1]), "+f"(c[2]), "+f"(c[3])
        : "r"(a[0]), "r"(a[1]), "r"(a[2]), "r"(a[3]), "r"(b[0]), "r"(b[1]));
}

__device__ __forceinline__ uint32_t pack_bf16x2(float x0, float x1) {
    __nv_bfloat16 h0 = __float2bfloat16(x0), h1 = __float2bfloat16(x1);
    return (uint32_t)__bfloat16_as_ushort(h0) | ((uint32_t)__bfloat16_as_ushort(h1) << 16);
}

// ================= tensor-core GEMM: C[M,256] = A[M,KTOT] @ W  ===============
// CTA tile 128(M) x 128(N); grid.x = 2 covers N=256. 8 warps = 2(M) x 4(N),
// warp tile 64x32 = 4 x 4 m16n8 fragments. Split-bf16 3-term fp32 emulation.
// Register prefetch + 2-stage SMEM double buffering.
// row_base: m-tile offset (for chunked launches).
// MODE 1: O1 = raw result (256-wide)
// MODE 2: n-half 0 -> O1 + bias1 (mu), n-half 1 -> O2 + bias2 (logvar)
#define PADK 40
#define TILE_B (128 * PADK * 2)           // 10240 bytes per tile
#define STAGE_B (4 * TILE_B)              // Ah, Al, Bh, Bl
#define SMEM_GEMM (2 * STAGE_B)           // 81920 bytes

template <int KTOT, int MODE>
__global__ __launch_bounds__(256, 1) void k_mma_gemm(
    const float* __restrict__ A,
    const __nv_bfloat16* __restrict__ Bhi, const __nv_bfloat16* __restrict__ Blo,
    float* __restrict__ O1, float* __restrict__ O2,
    const float* __restrict__ bias1, const float* __restrict__ bias2,
    int M, int row_base)
{
    extern __shared__ __align__(16) char smraw[];

    const int t    = threadIdx.x;
    const int row0 = row_base + blockIdx.y * 128;
    const int bn   = blockIdx.x * 128;
    const int wid  = t >> 5, lane = t & 31;
    const int wm0  = (wid & 1) * 64;
    const int wn0  = (wid >> 1) * 32;
    const int g    = lane >> 2, tq = lane & 3;

    float acc[4][4][4];
    #pragma unroll
    for (int i = 0; i < 4; i++)
        #pragma unroll
        for (int j = 0; j < 4; j++)
            #pragma unroll
            for (int q = 0; q < 4; q++) acc[i][j][q] = 0.f;

    const int r_ld = t >> 1;          // 0..127
    const int k_ld = (t & 1) * 16;    // 0 or 16
    const bool a_ok = (row0 + r_ld) < M;
    const float* a_base = A + (size_t)(row0 + r_ld) * KTOT + k_ld;
    const size_t b_base = (size_t)(bn + r_ld) * KTOT + k_ld;

    float  fA[16];
    uint4  rBh[2], rBl[2];

    auto ldA = [&](int kc) {
        if (a_ok) {
            const float4* p = (const float4*)(a_base + kc);
            float4 v0 = p[0], v1 = p[1], v2 = p[2], v3 = p[3];
            fA[0]=v0.x; fA[1]=v0.y; fA[2]=v0.z; fA[3]=v0.w;
            fA[4]=v1.x; fA[5]=v1.y; fA[6]=v1.z; fA[7]=v1.w;
            fA[8]=v2.x; fA[9]=v2.y; fA[10]=v2.z; fA[11]=v2.w;
            fA[12]=v3.x; fA[13]=v3.y; fA[14]=v3.z; fA[15]=v3.w;
        } else {
            #pragma unroll
            for (int j = 0; j < 16; j++) fA[j] = 0.f;
        }
        const uint4* ph = (const uint4*)(Bhi + b_base + kc);
        const uint4* pl = (const uint4*)(Blo + b_base + kc);
        rBh[0] = ph[0]; rBh[1] = ph[1];
        rBl[0] = pl[0]; rBl[1] = pl[1];
    };

    ldA(0);  // prefetch chunk 0

    const int NCH = KTOT / 32;
    for (int c = 0; c < NCH; c++) {
        char* stg = smraw + (c & 1) * STAGE_B;
        __nv_bfloat16* Ah = (__nv_bfloat16*)(stg);
        __nv_bfloat16* Al = (__nv_bfloat16*)(stg + TILE_B);
        __nv_bfloat16* Bh = (__nv_bfloat16*)(stg + 2 * TILE_B);
        __nv_bfloat16* Bl = (__nv_bfloat16*)(stg + 3 * TILE_B);

        // ---- store prefetched chunk to SMEM (A: fp32 -> bf16 hi/lo split) ----
        {
            uint32_t hu[8], lu[8];
            #pragma unroll
            for (int j = 0; j < 8; j++) {
                float x0 = fA[2*j], x1 = fA[2*j+1];
                __nv_bfloat16 h0 = __float2bfloat16(x0), h1 = __float2bfloat16(x1);
                float r0 = x0 - __bfloat162float(h0);
                float r1 = x1 - __bfloat162float(h1);
                hu[j] = (uint32_t)__bfloat16_as_ushort(h0) |
                        ((uint32_t)__bfloat16_as_ushort(h1) << 16);
                lu[j] = pack_bf16x2(r0, r1);
            }
            int o = r_ld * PADK + k_ld;
            *(uint4*)&Ah[o]     = make_uint4(hu[0], hu[1], hu[2], hu[3]);
            *(uint4*)&Ah[o + 8] = make_uint4(hu[4], hu[5], hu[6], hu[7]);
            *(uint4*)&Al[o]     = make_uint4(lu[0], lu[1], lu[2], lu[3]);
            *(uint4*)&Al[o + 8] = make_uint4(lu[4], lu[5], lu[6], lu[7]);
            *(uint4*)&Bh[o]     = rBh[0];
            *(uint4*)&Bh[o + 8] = rBh[1];
            *(uint4*)&Bl[o]     = rBl[0];
            *(uint4*)&Bl[o + 8] = rBl[1];
        }
        __syncthreads();   // single sync per chunk (double-buffered stages)

        // ---- prefetch next chunk (latency overlapped with MMA below) ----
        if (c + 1 < NCH) ldA((c + 1) * 32);

        #pragma unroll
        for (int kk = 0; kk < 32; kk += 16) {
            uint32_t bh[4][2], bl[4][2];
            #pragma unroll
            for (int nf = 0; nf < 4; nf++) {
                int n = (wn0 + nf * 8 + g) * PADK + kk + tq * 2;
                bh[nf][0] = *(const uint32_t*)&Bh[n];
                bh[nf][1] = *(const uint32_t*)&Bh[n + 8];
                bl[nf][0] = *(const uint32_t*)&Bl[n];
                bl[nf][1] = *(const uint32_t*)&Bl[n + 8];
            }
            #pragma unroll
            for (int mf = 0; mf < 4; mf++) {
                int m = (wm0 + mf * 16 + g) * PADK + kk + tq * 2;
                uint32_t ah[4], al[4];
                ah[0] = *(const uint32_t*)&Ah[m];
                ah[1] = *(const uint32_t*)&Ah[m + 8 * PADK];
                ah[2] = *(const uint32_t*)&Ah[m + 8];
                ah[3] = *(const uint32_t*)&Ah[m + 8 * PADK + 8];
                al[0] = *(const uint32_t*)&Al[m];
                al[1] = *(const uint32_t*)&Al[m + 8 * PADK];
                al[2] = *(const uint32_t*)&Al[m + 8];
                al[3] = *(const uint32_t*)&Al[m + 8 * PADK + 8];
                #pragma unroll
                for (int nf = 0; nf < 4; nf++) {
                    mma_bf16(acc[mf][nf], ah, bh[nf]);  // hi*hi
                    mma_bf16(acc[mf][nf], ah, bl[nf]);  // hi*lo
                    mma_bf16(acc[mf][nf], al, bh[nf]);  // lo*hi
                }
            }
        }
    }

    // ---- epilogue: registers -> global ----
    #pragma unroll
    for (int mf = 0; mf < 4; mf++) {
        int mA = row0 + wm0 + mf * 16 + g;   // rows for c0,c1
        int mB = mA + 8;                     // rows for c2,c3
        if (MODE == 1) {
            #pragma unroll
            for (int nf = 0; nf < 4; nf++) {
                int n = bn + wn0 + nf * 8 + tq * 2;
                if (mA < M)
                    *(float2*)(O1 + (size_t)mA * 256 + n) =
                        make_float2(acc[mf][nf][0], acc[mf][nf][1]);
                if (mB < M)
                    *(float2*)(O1 + (size_t)mB * 256 + n) =
                        make_float2(acc[mf][nf][2], acc[mf][nf][3]);
            }
        } else {
            const float* bs = (bn == 0) ? bias1 : bias2;
            float* Oo = (bn == 0) ? O1 : O2;
            #pragma unroll
            for (int nf = 0; nf < 4; nf++) {
                int col = wn0 + nf * 8 + tq * 2;  // 0..127 within half
                float b0 = bs[col], b1 = bs[col + 1];
                if (mA < M)
                    *(float2*)(Oo + (size_t)mA * 128 + col) =
                        make_float2(acc[mf][nf][0] + b0, acc[mf][nf][1] + b1);
                if (mB < M)
                    *(float2*)(Oo + (size_t)mB * 128 + col) =
                        make_float2(acc[mf][nf][2] + b0, acc[mf][nf][3] + b1);
            }
        }
    }
}

// ---------------- prep A: dtype probe + cnt/deg init (feeds CSR chain) -------
__global__ void k_prep_graph(const int* __restrict__ ei_raw,
                             int* __restrict__ cnt, float* __restrict__ deg) {
    int idx = blockIdx.x * blockDim.x + threadIdx.x;
    if (idx == 0) {
        // dtype probe: node ids < 50000, so int64 => odd 32-bit words all zero
        int allzero = 1;
        #pragma unroll
        for (int i = 0; i < 8; i++)
            if (ei_raw[2 * i + 1] != 0) allzero = 0;
        g_is64 = allzero;
    }
    if (idx < NN) { cnt[idx] = 0; deg[idx] = 1.0f; }  // self-loop weight
}

// ---------------- prep B: weight transpose + bf16 split (feeds GEMMs) --------
__global__ void k_prep_w(const float* __restrict__ W1,
                         const float* __restrict__ Wmu, const float* __restrict__ Wlv,
                         __nv_bfloat16* __restrict__ w1h, __nv_bfloat16* __restrict__ w1l,
                         __nv_bfloat16* __restrict__ w2h, __nv_bfloat16* __restrict__ w2l) {
    int idx = blockIdx.x * blockDim.x + threadIdx.x;
    if (idx < IN_F * HID_F) {
        int k = idx >> 8, n = idx & 255;
        float v = W1[(size_t)k * HID_F + n];
        __nv_bfloat16 h = __float2bfloat16(v);
        __nv_bfloat16 l = __float2bfloat16(v - __bfloat162float(h));
        w1h[(size_t)n * IN_F + k] = h;
        w1l[(size_t)n * IN_F + k] = l;
    }
    if (idx < HID_F * HID_F) {
        int k = idx >> 8, n = idx & 255;
        float v = (n < 128) ? Wmu[(size_t)k * LAT_F + n] : Wlv[(size_t)k * LAT_F + (n - 128)];
        __nv_bfloat16 h = __float2bfloat16(v);
        __nv_bfloat16 l = __float2bfloat16(v - __bfloat162float(h));
        w2h[(size_t)n * HID_F + k] = h;
        w2l[(size_t)n * HID_F + k] = l;
    }
}

__device__ __forceinline__ int load_idx(const void* ei, long long pos, int is64) {
    if (is64) return (int)((const long long*)ei)[pos];
    return ((const int*)ei)[pos];
}

// ---------------- CSR construction -------------------------------------------
__global__ void k_hist(int* cnt, float* deg, const void* __restrict__ ei,
                       const float* __restrict__ w, int e_cnt) {
    int e = blockIdx.x * blockDim.x + threadIdx.x;
    if (e < e_cnt) {
        int d = load_idx(ei, (long long)e_cnt + e, g_is64);
        if ((unsigned)d < NN) {
            atomicAdd(&cnt[d], 1);
            atomicAdd(&deg[d], w[e]);
        }
    }
}

// ---- 3-phase scan over cnt[0..n): rowptr (exclusive+1) and fill cursors ----
// scan1 also computes dis = rsqrt(deg) (independent elementwise, same grid).
__device__ __forceinline__ int block_scan_incl(int x, int* ws) {
    int lane = threadIdx.x & 31, w = threadIdx.x >> 5;
    int v = x;
    #pragma unroll
    for (int o = 1; o < 32; o <<= 1) {
        int t = __shfl_up_sync(0xFFFFFFFFu, v, o);
        if (lane >= o) v += t;
    }
    if (lane == 31) ws[w] = v;
    __syncthreads();
    if (w == 0) {
        int s = (lane < 8) ? ws[lane] : 0;
        #pragma unroll
        for (int o = 1; o < 8; o <<= 1) {
            int t = __shfl_up_sync(0xFFFFFFFFu, s, o);
            if (lane >= o) s += t;
        }
        if (lane < 8) ws[lane] = s;
    }
    __syncthreads();
    return v + (w > 0 ? ws[w - 1] : 0);
}
__global__ void k_scan1(const int* __restrict__ cnt, int* __restrict__ incl,
                        int* __restrict__ part, const float* __restrict__ deg,
                        float* __restrict__ dis, int n) {
    __shared__ int ws[8];
    int i = blockIdx.x * 256 + threadIdx.x;
    if (i < n) dis[i] = rsqrtf(deg[i]);
    int x = (i < n) ? cnt[i] : 0;
    int v = block_scan_incl(x, ws);
    if (i < n) incl[i] = v;
    if (threadIdx.x == 255) part[blockIdx.x] = v;
}
__global__ void k_scan2(int* part, int nb) {  // single block, nb <= 256
    __shared__ int ws[8];
    int tid = threadIdx.x;
    int x = (tid < nb) ? part[tid] : 0;
    int v = block_scan_incl(x, ws);
    if (tid < nb) part[tid] = v - x;  // exclusive block offsets
}
__global__ void k_scan3(const int* __restrict__ cnt, int* __restrict__ incl_fill,
                        const int* __restrict__ part, int* __restrict__ rowptr, int n) {
    int i = blockIdx.x * 256 + threadIdx.x;
    if (i < n) {
        int v = incl_fill[i] + part[blockIdx.x];
        rowptr[i + 1] = v;
        incl_fill[i] = v - cnt[i];  // becomes fill cursor (exclusive)
    }
    if (i == 0) rowptr[0] = 0;
}
__global__ void k_csr_fill(const void* __restrict__ ei, const float* __restrict__ ea,
                           const float* __restrict__ dis, int* __restrict__ fill,
                           int* __restrict__ col, float* __restrict__ val, int e_cnt) {
    int e = blockIdx.x * blockDim.x + threadIdx.x;
    if (e >= e_cnt) return;
    int is64 = g_is64;
    int s = load_idx(ei, e, is64);
    int d = load_idx(ei, (long long)e_cnt + e, is64);
    if ((unsigned)s >= NN || (unsigned)d >= NN) return;
    int p = atomicAdd(&fill[d], 1);
    col[p] = s;
    val[p] = dis[s] * ea[e] * dis[d];
}

// ---------------- CSR gather: out[n,:] = d2*h(n,:) + sum val*h(col,:) --------
// PASS 1: h = identity (m = m1). PASS 2: h = relu(m + b1) (m = agg1).
// 64 threads per node (one float4 per thread), 4 nodes per 256-thread block.
// [node_base, node_end): node range for chunked launches.
template <int PASS>
__global__ __launch_bounds__(256, 4) void k_gather(
    const float* __restrict__ m, float* __restrict__ out,
    const int* __restrict__ rowptr, const int* __restrict__ col,
    const float* __restrict__ val, const float* __restrict__ dis,
    const float* __restrict__ b1, int node_base, int node_end)
{
    int node = node_base + blockIdx.x * 4 + (threadIdx.x >> 6);
    if (node >= node_end) return;
    int part = threadIdx.x & 63;  // float4 slot within 256-wide row
    int r0 = rowptr[node], r1 = rowptr[node + 1];
    float dv = dis[node];
    float d2 = dv * dv;

    float4 b = make_float4(0.f, 0.f, 0.f, 0.f);
    if (PASS == 2) b = *(const float4*)(b1 + part * 4);

    auto act = [&](float4 a) -> float4 {
        if (PASS == 2) {
            a.x = fmaxf(a.x + b.x, 0.f); a.y = fmaxf(a.y + b.y, 0.f);
            a.z = fmaxf(a.z + b.z, 0.f); a.w = fmaxf(a.w + b.w, 0.f);
        }
        return a;
    };

    // self-loop term
    float4 s = act(*(const float4*)(m + ((size_t)node << 8) + part * 4));
    float4 acc = make_float4(s.x * d2, s.y * d2, s.z * d2, s.w * d2);

    int j = r0;
    for (; j + 4 <= r1; j += 4) {
        int   c0 = col[j], c1 = col[j+1], c2 = col[j+2], c3 = col[j+3];
        float v0 = val[j], v1 = val[j+1], v2 = val[j+2], v3 = val[j+3];
        float4 a0 = *(const float4*)(m + ((size_t)c0 << 8) + part * 4);
        float4 a1 = *(const float4*)(m + ((size_t)c1 << 8) + part * 4);
        float4 a2 = *(const float4*)(m + ((size_t)c2 << 8) + part * 4);
        float4 a3 = *(const float4*)(m + ((size_t)c3 << 8) + part * 4);
        a0 = act(a0); a1 = act(a1); a2 = act(a2); a3 = act(a3);
        acc.x += v0 * a0.x + v1 * a1.x + v2 * a2.x + v3 * a3.x;
        acc.y += v0 * a0.y + v1 * a1.y + v2 * a2.y + v3 * a3.y;
        acc.z += v0 * a0.z + v1 * a1.z + v2 * a2.z + v3 * a3.z;
        acc.w += v0 * a0.w + v1 * a1.w + v2 * a2.w + v3 * a3.w;
    }
    for (; j < r1; j++) {
        int c0 = col[j];
        float v0 = val[j];
        float4 a0 = act(*(const float4*)(m + ((size_t)c0 << 8) + part * 4));
        acc.x += v0 * a0.x; acc.y += v0 * a0.y;
        acc.z += v0 * a0.z; acc.w += v0 * a0.w;
    }
    *(float4*)(out + ((size_t)node << 8) + part * 4) = acc;
}

// ---------------- launch ------------------------------------------------------
extern "C" void kernel_launch(void* const* d_in, const int* in_sizes, int n_in,
                              void* d_out, int out_size) {
    const float* x    = (const float*)d_in[0];
    const void*  ei   = d_in[1];
    const float* ea   = (const float*)d_in[2];
    const float* W1   = (const float*)d_in[3];
    const float* b1   = (const float*)d_in[4];
    const float* Wmu  = (const float*)d_in[5];
    const float* bmu  = (const float*)d_in[6];
    const float* Wlv  = (const float*)d_in[7];
    const float* blv  = (const float*)d_in[8];
    float* out = (float*)d_out;

    float *m1, *agg1, *agg2, *dis, *deg, *val;
    int *cnt, *rowptr, *fill, *part, *col;
    __nv_bfloat16 *w1h, *w1l, *w2h, *w2l;
    cudaGetSymbolAddress((void**)&m1, g_m1);
    cudaGetSymbolAddress((void**)&agg1, g_agg1);
    cudaGetSymbolAddress((void**)&agg2, g_agg2);
    cudaGetSymbolAddress((void**)&dis, g_dis);
    cudaGetSymbolAddress((void**)&deg, g_deg);
    cudaGetSymbolAddress((void**)&cnt, g_cnt);
    cudaGetSymbolAddress((void**)&rowptr, g_rowptr);
    cudaGetSymbolAddress((void**)&fill, g_fill);
    cudaGetSymbolAddress((void**)&part, g_part);
    cudaGetSymbolAddress((void**)&col, g_col);
    cudaGetSymbolAddress((void**)&val, g_val);
    cudaGetSymbolAddress((void**)&w1h, g_W1T_hi);
    cudaGetSymbolAddress((void**)&w1l, g_W1T_lo);
    cudaGetSymbolAddress((void**)&w2h, g_W2T_hi);
    cudaGetSymbolAddress((void**)&w2l, g_W2T_lo);

    const int N = NN, E = EE;
    const int NB = (N + 255) / 256;  // 196 scan blocks

    cudaFuncSetAttribute(k_mma_gemm<IN_F, 1>,
                         cudaFuncAttributeMaxDynamicSharedMemorySize, SMEM_GEMM);
    cudaFuncSetAttribute(k_mma_gemm<HID_F, 2>,
                         cudaFuncAttributeMaxDynamicSharedMemorySize, SMEM_GEMM);

    // fork stream + events
    cudaStream_t s2;
    cudaStreamCreateWithFlags(&s2, cudaStreamNonBlocking);
    cudaEvent_t evFork, evCSR, evJoin, evG[4];
    cudaEventCreateWithFlags(&evFork, cudaEventDisableTiming);
    cudaEventCreateWithFlags(&evCSR, cudaEventDisableTiming);
    cudaEventCreateWithFlags(&evJoin, cudaEventDisableTiming);
    for (int c = 0; c < 4; c++) cudaEventCreateWithFlags(&evG[c], cudaEventDisableTiming);

    // fork s2 immediately; CSR chain runs there, hidden under prep_w + GEMM1
    cudaEventRecord(evFork, 0);
    cudaStreamWaitEvent(s2, evFork, 0);

    // s2: probe + init, then CSR build
    k_prep_graph<<<NB, 256, 0, s2>>>((const int*)ei, cnt, deg);
    k_hist<<<(E + 255) / 256, 256, 0, s2>>>(cnt, deg, ei, ea, E);
    k_scan1<<<NB, 256, 0, s2>>>(cnt, fill, part, deg, dis, N);
    k_scan2<<<1, 256, 0, s2>>>(part, NB);
    k_scan3<<<NB, 256, 0, s2>>>(cnt, fill, part, rowptr, N);
    k_csr_fill<<<(E + 255) / 256, 256, 0, s2>>>(ei, ea, dis, fill, col, val, E);
    cudaEventRecord(evCSR, s2);

    // s0: weight conversion, then GEMM1 (overlapped with CSR build)
    k_prep_w<<<(IN_F * HID_F + 255) / 256, 256>>>(W1, Wmu, Wlv, w1h, w1l, w2h, w2l);
    const dim3 gg(2, (N + 127) / 128);  // 2 n-tiles x 391 m-tiles
    k_mma_gemm<IN_F, 1><<<gg, 256, SMEM_GEMM>>>(x, w1h, w1l, m1,
                                                nullptr, nullptr, nullptr, N, 0);

    // join: gather1 needs both m1 and the CSR
    cudaStreamWaitEvent(0, evCSR, 0);

    // gather1 (full): agg1 = dis^2*m1[dst] + sum val*m1[src]
    k_gather<1><<<(N + 3) / 4, 256>>>(m1, agg1, rowptr, col, val, dis,
                                      nullptr, 0, N);

    // chunk-pipelined: gather2 chunk c (s0)  ->  GEMM2 chunk c (s2)
    // gather2: agg2 = dis^2*h[dst] + sum val*h[src], h = relu(agg1+b1) on the fly
    // GEMM2:   [mu | logvar] = agg2 @ [Wmu | Wlv] + [bmu | blv]
    const int CHUNK_N = 98 * 128;  // 12544 nodes per chunk (98 m-tiles)
    for (int c = 0; c < 4; c++) {
        int n0 = c * CHUNK_N;
        int n1 = (n0 + CHUNK_N < N) ? n0 + CHUNK_N : N;
        int nodes = n1 - n0;
        k_gather<2><<<(nodes + 3) / 4, 256>>>(agg1, agg2, rowptr, col, val, dis,
                                              b1, n0, n1);
        cudaEventRecord(evG[c], 0);
        cudaStreamWaitEvent(s2, evG[c], 0);
        dim3 g2(2, (nodes + 127) / 128);
        k_mma_gemm<HID_F, 2><<<g2, 256, SMEM_GEMM, s2>>>(
            agg2, w2h, w2l, out, out + (size_t)N * LAT_F, bmu, blv, N, n0);
    }

    // join s2 back into the origin stream before capture ends
    cudaEventRecord(evJoin, s2);
    cudaStreamWaitEvent(0, evJoin, 0);

    cudaEventDestroy(evFork);
    cudaEventDestroy(evCSR);
    cudaEventDestroy(evJoin);
    for (int c = 0; c < 4; c++) cudaEventDestroy(evG[c]);
    cudaStreamDestroy(s2);
}

// round 15
// speedup vs baseline: 1.0263x; 1.0263x over previous
#include <cuda_runtime.h>
#include <cuda_bf16.h>
#include <cstdint>

// Problem constants (fixed by the dataset)
#define NN 50000
#define EE 800000
#define IN_F 512
#define HID_F 256
#define LAT_F 128

// ---------------- scratch (static device globals; no runtime alloc) ----------
__device__ __align__(16) float g_m1[NN * HID_F];    // x @ W1
__device__ __align__(16) float g_agg1[NN * HID_F];  // layer-1 aggregate (pre-activation)
__device__ __align__(16) float g_agg2[NN * HID_F];  // layer-2 aggregate
__device__ float g_dis[NN];                         // rsqrt(deg)
__device__ float g_deg[NN];                         // weighted degree accum
__device__ int   g_cnt[NN];                         // incoming-edge count
__device__ int   g_rowptr[NN + 1];                  // CSR row pointers
__device__ int   g_fill[NN];                        // scan temp / fill cursors
__device__ int   g_part[256];                       // scan block partials
__device__ int   g_col[EE];                         // CSR: src per edge (sorted by dst)
__device__ float g_val[EE];                         // CSR: precomputed norm per edge
__device__ int   g_is64;                            // edge_index dtype flag

// Pre-transposed, bf16 hi/lo split weights: [N, K] K-major (= B col-major for mma)
__device__ __align__(16) __nv_bfloat16 g_W1T_hi[HID_F * IN_F];
__device__ __align__(16) __nv_bfloat16 g_W1T_lo[HID_F * IN_F];
__device__ __align__(16) __nv_bfloat16 g_W2T_hi[HID_F * HID_F];  // [256 (mu|lv), 256]
__device__ __align__(16) __nv_bfloat16 g_W2T_lo[HID_F * HID_F];

// ---------------- warp mma (Ampere-era PTX; no arch-feature gating) ----------
__device__ __forceinline__ void mma_bf16(float* c, const uint32_t* a, const uint32_t* b) {
    asm volatile(
        "mma.sync.aligned.m16n8k16.row.col.f32.bf16.bf16.f32 "
        "{%0,%1,%2,%3}, {%4,%5,%6,%7}, {%8,%9}, {%0,%1,%2,%3};"
        : "+f"(c[0]), "+f"(c[1]), "+f"(c[2]), "+f"(c[3])
        : "r"(a[0]), "r"(a[1]), "r"(a[2]), "r"(a[3]), "r"(b[0]), "r"(b[1]));
}

__device__ __forceinline__ uint32_t pack_bf16x2(float x0, float x1) {
    __nv_bfloat16 h0 = __float2bfloat16(x0), h1 = __float2bfloat16(x1);
    return (uint32_t)__bfloat16_as_ushort(h0) | ((uint32_t)__bfloat16_as_ushort(h1) << 16);
}

// ================= tensor-core GEMM: C[M,256] = A[M,KTOT] @ W  ===============
// CTA tile 128(M) x 128(N); grid.x = 2 covers N=256. 8 warps = 2(M) x 4(N),
// warp tile 64x32 = 4 x 4 m16n8 fragments. Split-bf16 3-term fp32 emulation.
// Register prefetch + 2-stage SMEM double buffering; 2 CTAs/SM (160KB SMEM/SM)
// so a co-resident CTA fills issue slots across syncs.
// MODE 1: O1 = raw result (256-wide)
// MODE 2: n-half 0 -> O1 + bias1 (mu), n-half 1 -> O2 + bias2 (logvar)
#define PADK 40
#define TILE_B (128 * PADK * 2)           // 10240 bytes per tile
#define STAGE_B (4 * TILE_B)              // Ah, Al, Bh, Bl
#define SMEM_GEMM (2 * STAGE_B)           // 81920 bytes

template <int KTOT, int MODE>
__global__ __launch_bounds__(256, 2) void k_mma_gemm(
    const float* __restrict__ A,
    const __nv_bfloat16* __restrict__ Bhi, const __nv_bfloat16* __restrict__ Blo,
    float* __restrict__ O1, float* __restrict__ O2,
    const float* __restrict__ bias1, const float* __restrict__ bias2, int M)
{
    extern __shared__ __align__(16) char smraw[];

    const int t    = threadIdx.x;
    const int row0 = blockIdx.y * 128;
    const int bn   = blockIdx.x * 128;
    const int wid  = t >> 5, lane = t & 31;
    const int wm0  = (wid & 1) * 64;
    const int wn0  = (wid >> 1) * 32;
    const int g    = lane >> 2, tq = lane & 3;

    float acc[4][4][4];
    #pragma unroll
    for (int i = 0; i < 4; i++)
        #pragma unroll
        for (int j = 0; j < 4; j++)
            #pragma unroll
            for (int q = 0; q < 4; q++) acc[i][j][q] = 0.f;

    const int r_ld = t >> 1;          // 0..127
    const int k_ld = (t & 1) * 16;    // 0 or 16
    const bool a_ok = (row0 + r_ld) < M;
    const float* a_base = A + (size_t)(row0 + r_ld) * KTOT + k_ld;
    const size_t b_base = (size_t)(bn + r_ld) * KTOT + k_ld;

    float  fA[16];
    uint4  rBh[2], rBl[2];

    auto ldA = [&](int kc) {
        if (a_ok) {
            const float4* p = (const float4*)(a_base + kc);
            float4 v0 = p[0], v1 = p[1], v2 = p[2], v3 = p[3];
            fA[0]=v0.x; fA[1]=v0.y; fA[2]=v0.z; fA[3]=v0.w;
            fA[4]=v1.x; fA[5]=v1.y; fA[6]=v1.z; fA[7]=v1.w;
            fA[8]=v2.x; fA[9]=v2.y; fA[10]=v2.z; fA[11]=v2.w;
            fA[12]=v3.x; fA[13]=v3.y; fA[14]=v3.z; fA[15]=v3.w;
        } else {
            #pragma unroll
            for (int j = 0; j < 16; j++) fA[j] = 0.f;
        }
        const uint4* ph = (const uint4*)(Bhi + b_base + kc);
        const uint4* pl = (const uint4*)(Blo + b_base + kc);
        rBh[0] = ph[0]; rBh[1] = ph[1];
        rBl[0] = pl[0]; rBl[1] = pl[1];
    };

    ldA(0);  // prefetch chunk 0

    const int NCH = KTOT / 32;
    for (int c = 0; c < NCH; c++) {
        char* stg = smraw + (c & 1) * STAGE_B;
        __nv_bfloat16* Ah = (__nv_bfloat16*)(stg);
        __nv_bfloat16* Al = (__nv_bfloat16*)(stg + TILE_B);
        __nv_bfloat16* Bh = (__nv_bfloat16*)(stg + 2 * TILE_B);
        __nv_bfloat16* Bl = (__nv_bfloat16*)(stg + 3 * TILE_B);

        // ---- store prefetched chunk to SMEM (A: fp32 -> bf16 hi/lo split) ----
        {
            uint32_t hu[8], lu[8];
            #pragma unroll
            for (int j = 0; j < 8; j++) {
                float x0 = fA[2*j], x1 = fA[2*j+1];
                __nv_bfloat16 h0 = __float2bfloat16(x0), h1 = __float2bfloat16(x1);
                float r0 = x0 - __bfloat162float(h0);
                float r1 = x1 - __bfloat162float(h1);
                hu[j] = (uint32_t)__bfloat16_as_ushort(h0) |
                        ((uint32_t)__bfloat16_as_ushort(h1) << 16);
                lu[j] = pack_bf16x2(r0, r1);
            }
            int o = r_ld * PADK + k_ld;
            *(uint4*)&Ah[o]     = make_uint4(hu[0], hu[1], hu[2], hu[3]);
            *(uint4*)&Ah[o + 8] = make_uint4(hu[4], hu[5], hu[6], hu[7]);
            *(uint4*)&Al[o]     = make_uint4(lu[0], lu[1], lu[2], lu[3]);
            *(uint4*)&Al[o + 8] = make_uint4(lu[4], lu[5], lu[6], lu[7]);
            *(uint4*)&Bh[o]     = rBh[0];
            *(uint4*)&Bh[o + 8] = rBh[1];
            *(uint4*)&Bl[o]     = rBl[0];
            *(uint4*)&Bl[o + 8] = rBl[1];
        }
        __syncthreads();   // single sync per chunk (double-buffered stages)

        // ---- prefetch next chunk (latency overlapped with MMA below) ----
        if (c + 1 < NCH) ldA((c + 1) * 32);

        #pragma unroll
        for (int kk = 0; kk < 32; kk += 16) {
            uint32_t bh[4][2], bl[4][2];
            #pragma unroll
            for (int nf = 0; nf < 4; nf++) {
                int n = (wn0 + nf * 8 + g) * PADK + kk + tq * 2;
                bh[nf][0] = *(const uint32_t*)&Bh[n];
                bh[nf][1] = *(const uint32_t*)&Bh[n + 8];
                bl[nf][0] = *(const uint32_t*)&Bl[n];
                bl[nf][1] = *(const uint32_t*)&Bl[n + 8];
            }
            #pragma unroll
            for (int mf = 0; mf < 4; mf++) {
                int m = (wm0 + mf * 16 + g) * PADK + kk + tq * 2;
                uint32_t ah[4], al[4];
                ah[0] = *(const uint32_t*)&Ah[m];
                ah[1] = *(const uint32_t*)&Ah[m + 8 * PADK];
                ah[2] = *(const uint32_t*)&Ah[m + 8];
                ah[3] = *(const uint32_t*)&Ah[m + 8 * PADK + 8];
                al[0] = *(const uint32_t*)&Al[m];
                al[1] = *(const uint32_t*)&Al[m + 8 * PADK];
                al[2] = *(const uint32_t*)&Al[m + 8];
                al[3] = *(const uint32_t*)&Al[m + 8 * PADK + 8];
                #pragma unroll
                for (int nf = 0; nf < 4; nf++) {
                    mma_bf16(acc[mf][nf], ah, bh[nf]);  // hi*hi
                    mma_bf16(acc[mf][nf], ah, bl[nf]);  // hi*lo
                    mma_bf16(acc[mf][nf], al, bh[nf]);  // lo*hi
                }
            }
        }
    }

    // ---- epilogue: registers -> global ----
    #pragma unroll
    for (int mf = 0; mf < 4; mf++) {
        int mA = row0 + wm0 + mf * 16 + g;   // rows for c0,c1
        int mB = mA + 8;                     // rows for c2,c3
        if (MODE == 1) {
            #pragma unroll
            for (int nf = 0; nf < 4; nf++) {
                int n = bn + wn0 + nf * 8 + tq * 2;
                if (mA < M)
                    *(float2*)(O1 + (size_t)mA * 256 + n) =
                        make_float2(acc[mf][nf][0], acc[mf][nf][1]);
                if (mB < M)
                    *(float2*)(O1 + (size_t)mB * 256 + n) =
                        make_float2(acc[mf][nf][2], acc[mf][nf][3]);
            }
        } else {
            const float* bs = (bn == 0) ? bias1 : bias2;
            float* Oo = (bn == 0) ? O1 : O2;
            #pragma unroll
            for (int nf = 0; nf < 4; nf++) {
                int col = wn0 + nf * 8 + tq * 2;  // 0..127 within half
                float b0 = bs[col], b1 = bs[col + 1];
                if (mA < M)
                    *(float2*)(Oo + (size_t)mA * 128 + col) =
                        make_float2(acc[mf][nf][0] + b0, acc[mf][nf][1] + b1);
                if (mB < M)
                    *(float2*)(Oo + (size_t)mB * 128 + col) =
                        make_float2(acc[mf][nf][2] + b0, acc[mf][nf][3] + b1);
            }
        }
    }
}

// ---------------- prep A: dtype probe + cnt/deg init (feeds CSR chain) -------
__global__ void k_prep_graph(const int* __restrict__ ei_raw,
                             int* __restrict__ cnt, float* __restrict__ deg) {
    int idx = blockIdx.x * blockDim.x + threadIdx.x;
    if (idx == 0) {
        // dtype probe: node ids < 50000, so int64 => odd 32-bit words all zero
        int allzero = 1;
        #pragma unroll
        for (int i = 0; i < 8; i++)
            if (ei_raw[2 * i + 1] != 0) allzero = 0;
        g_is64 = allzero;
    }
    if (idx < NN) { cnt[idx] = 0; deg[idx] = 1.0f; }  // self-loop weight
}

// ---------------- prep B: weight transpose + bf16 split (feeds GEMMs) --------
__global__ void k_prep_w(const float* __restrict__ W1,
                         const float* __restrict__ Wmu, const float* __restrict__ Wlv,
                         __nv_bfloat16* __restrict__ w1h, __nv_bfloat16* __restrict__ w1l,
                         __nv_bfloat16* __restrict__ w2h, __nv_bfloat16* __restrict__ w2l) {
    int idx = blockIdx.x * blockDim.x + threadIdx.x;
    if (idx < IN_F * HID_F) {
        int k = idx >> 8, n = idx & 255;
        float v = W1[(size_t)k * HID_F + n];
        __nv_bfloat16 h = __float2bfloat16(v);
        __nv_bfloat16 l = __float2bfloat16(v - __bfloat162float(h));
        w1h[(size_t)n * IN_F + k] = h;
        w1l[(size_t)n * IN_F + k] = l;
    }
    if (idx < HID_F * HID_F) {
        int k = idx >> 8, n = idx & 255;
        float v = (n < 128) ? Wmu[(size_t)k * LAT_F + n] : Wlv[(size_t)k * LAT_F + (n - 128)];
        __nv_bfloat16 h = __float2bfloat16(v);
        __nv_bfloat16 l = __float2bfloat16(v - __bfloat162float(h));
        w2h[(size_t)n * HID_F + k] = h;
        w2l[(size_t)n * HID_F + k] = l;
    }
}

__device__ __forceinline__ int load_idx(const void* ei, long long pos, int is64) {
    if (is64) return (int)((const long long*)ei)[pos];
    return ((const int*)ei)[pos];
}

// ---------------- CSR construction -------------------------------------------
__global__ void k_hist(int* cnt, float* deg, const void* __restrict__ ei,
                       const float* __restrict__ w, int e_cnt) {
    int e = blockIdx.x * blockDim.x + threadIdx.x;
    if (e < e_cnt) {
        int d = load_idx(ei, (long long)e_cnt + e, g_is64);
        if ((unsigned)d < NN) {
            atomicAdd(&cnt[d], 1);
            atomicAdd(&deg[d], w[e]);
        }
    }
}

// ---- 3-phase scan over cnt[0..n): rowptr (exclusive+1) and fill cursors ----
// scan1 also computes dis = rsqrt(deg) (independent elementwise, same grid).
__device__ __forceinline__ int block_scan_incl(int x, int* ws) {
    int lane = threadIdx.x & 31, w = threadIdx.x >> 5;
    int v = x;
    #pragma unroll
    for (int o = 1; o < 32; o <<= 1) {
        int t = __shfl_up_sync(0xFFFFFFFFu, v, o);
        if (lane >= o) v += t;
    }
    if (lane == 31) ws[w] = v;
    __syncthreads();
    if (w == 0) {
        int s = (lane < 8) ? ws[lane] : 0;
        #pragma unroll
        for (int o = 1; o < 8; o <<= 1) {
            int t = __shfl_up_sync(0xFFFFFFFFu, s, o);
            if (lane >= o) s += t;
        }
        if (lane < 8) ws[lane] = s;
    }
    __syncthreads();
    return v + (w > 0 ? ws[w - 1] : 0);
}
__global__ void k_scan1(const int* __restrict__ cnt, int* __restrict__ incl,
                        int* __restrict__ part, const float* __restrict__ deg,
                        float* __restrict__ dis, int n) {
    __shared__ int ws[8];
    int i = blockIdx.x * 256 + threadIdx.x;
    if (i < n) dis[i] = rsqrtf(deg[i]);
    int x = (i < n) ? cnt[i] : 0;
    int v = block_scan_incl(x, ws);
    if (i < n) incl[i] = v;
    if (threadIdx.x == 255) part[blockIdx.x] = v;
}
__global__ void k_scan2(int* part, int nb) {  // single block, nb <= 256
    __shared__ int ws[8];
    int tid = threadIdx.x;
    int x = (tid < nb) ? part[tid] : 0;
    int v = block_scan_incl(x, ws);
    if (tid < nb) part[tid] = v - x;  // exclusive block offsets
}
__global__ void k_scan3(const int* __restrict__ cnt, int* __restrict__ incl_fill,
                        const int* __restrict__ part, int* __restrict__ rowptr, int n) {
    int i = blockIdx.x * 256 + threadIdx.x;
    if (i < n) {
        int v = incl_fill[i] + part[blockIdx.x];
        rowptr[i + 1] = v;
        incl_fill[i] = v - cnt[i];  // becomes fill cursor (exclusive)
    }
    if (i == 0) rowptr[0] = 0;
}
__global__ void k_csr_fill(const void* __restrict__ ei, const float* __restrict__ ea,
                           const float* __restrict__ dis, int* __restrict__ fill,
                           int* __restrict__ col, float* __restrict__ val, int e_cnt) {
    int e = blockIdx.x * blockDim.x + threadIdx.x;
    if (e >= e_cnt) return;
    int is64 = g_is64;
    int s = load_idx(ei, e, is64);
    int d = load_idx(ei, (long long)e_cnt + e, is64);
    if ((unsigned)s >= NN || (unsigned)d >= NN) return;
    int p = atomicAdd(&fill[d], 1);
    col[p] = s;
    val[p] = dis[s] * ea[e] * dis[d];
}

// ---------------- CSR gather: out[n,:] = d2*h(n,:) + sum val*h(col,:) --------
// PASS 1: h = identity (m = m1). PASS 2: h = relu(m + b1) (m = agg1).
// 64 threads per node (one float4 per thread), 4 nodes per 256-thread block.
template <int PASS>
__global__ __launch_bounds__(256, 4) void k_gather(
    const float* __restrict__ m, float* __restrict__ out,
    const int* __restrict__ rowptr, const int* __restrict__ col,
    const float* __restrict__ val, const float* __restrict__ dis,
    const float* __restrict__ b1)
{
    int node = blockIdx.x * 4 + (threadIdx.x >> 6);
    if (node >= NN) return;
    int part = threadIdx.x & 63;  // float4 slot within 256-wide row
    int r0 = rowptr[node], r1 = rowptr[node + 1];
    float dv = dis[node];
    float d2 = dv * dv;

    float4 b = make_float4(0.f, 0.f, 0.f, 0.f);
    if (PASS == 2) b = *(const float4*)(b1 + part * 4);

    auto act = [&](float4 a) -> float4 {
        if (PASS == 2) {
            a.x = fmaxf(a.x + b.x, 0.f); a.y = fmaxf(a.y + b.y, 0.f);
            a.z = fmaxf(a.z + b.z, 0.f); a.w = fmaxf(a.w + b.w, 0.f);
        }
        return a;
    };

    // self-loop term
    float4 s = act(*(const float4*)(m + ((size_t)node << 8) + part * 4));
    float4 acc = make_float4(s.x * d2, s.y * d2, s.z * d2, s.w * d2);

    int j = r0;
    for (; j + 4 <= r1; j += 4) {
        int   c0 = col[j], c1 = col[j+1], c2 = col[j+2], c3 = col[j+3];
        float v0 = val[j], v1 = val[j+1], v2 = val[j+2], v3 = val[j+3];
        float4 a0 = *(const float4*)(m + ((size_t)c0 << 8) + part * 4);
        float4 a1 = *(const float4*)(m + ((size_t)c1 << 8) + part * 4);
        float4 a2 = *(const float4*)(m + ((size_t)c2 << 8) + part * 4);
        float4 a3 = *(const float4*)(m + ((size_t)c3 << 8) + part * 4);
        a0 = act(a0); a1 = act(a1); a2 = act(a2); a3 = act(a3);
        acc.x += v0 * a0.x + v1 * a1.x + v2 * a2.x + v3 * a3.x;
        acc.y += v0 * a0.y + v1 * a1.y + v2 * a2.y + v3 * a3.y;
        acc.z += v0 * a0.z + v1 * a1.z + v2 * a2.z + v3 * a3.z;
        acc.w += v0 * a0.w + v1 * a1.w + v2 * a2.w + v3 * a3.w;
    }
    for (; j < r1; j++) {
        int c0 = col[j];
        float v0 = val[j];
        float4 a0 = act(*(const float4*)(m + ((size_t)c0 << 8) + part * 4));
        acc.x += v0 * a0.x; acc.y += v0 * a0.y;
        acc.z += v0 * a0.z; acc.w += v0 * a0.w;
    }
    *(float4*)(out + ((size_t)node << 8) + part * 4) = acc;
}

// ---------------- launch ------------------------------------------------------
extern "C" void kernel_launch(void* const* d_in, const int* in_sizes, int n_in,
                              void* d_out, int out_size) {
    const float* x    = (const float*)d_in[0];
    const void*  ei   = d_in[1];
    const float* ea   = (const float*)d_in[2];
    const float* W1   = (const float*)d_in[3];
    const float* b1   = (const float*)d_in[4];
    const float* Wmu  = (const float*)d_in[5];
    const float* bmu  = (const float*)d_in[6];
    const float* Wlv  = (const float*)d_in[7];
    const float* blv  = (const float*)d_in[8];
    float* out = (float*)d_out;

    float *m1, *agg1, *agg2, *dis, *deg, *val;
    int *cnt, *rowptr, *fill, *part, *col;
    __nv_bfloat16 *w1h, *w1l, *w2h, *w2l;
    cudaGetSymbolAddress((void**)&m1, g_m1);
    cudaGetSymbolAddress((void**)&agg1, g_agg1);
    cudaGetSymbolAddress((void**)&agg2, g_agg2);
    cudaGetSymbolAddress((void**)&dis, g_dis);
    cudaGetSymbolAddress((void**)&deg, g_deg);
    cudaGetSymbolAddress((void**)&cnt, g_cnt);
    cudaGetSymbolAddress((void**)&rowptr, g_rowptr);
    cudaGetSymbolAddress((void**)&fill, g_fill);
    cudaGetSymbolAddress((void**)&part, g_part);
    cudaGetSymbolAddress((void**)&col, g_col);
    cudaGetSymbolAddress((void**)&val, g_val);
    cudaGetSymbolAddress((void**)&w1h, g_W1T_hi);
    cudaGetSymbolAddress((void**)&w1l, g_W1T_lo);
    cudaGetSymbolAddress((void**)&w2h, g_W2T_hi);
    cudaGetSymbolAddress((void**)&w2l, g_W2T_lo);

    const int N = NN, E = EE;
    const int NB = (N + 255) / 256;  // 196 scan blocks

    cudaFuncSetAttribute(k_mma_gemm<IN_F, 1>,
                         cudaFuncAttributeMaxDynamicSharedMemorySize, SMEM_GEMM);
    cudaFuncSetAttribute(k_mma_gemm<HID_F, 2>,
                         cudaFuncAttributeMaxDynamicSharedMemorySize, SMEM_GEMM);

    // fork stream + events for CSR-build / GEMM1 overlap
    cudaStream_t s2;
    cudaStreamCreateWithFlags(&s2, cudaStreamNonBlocking);
    cudaEvent_t evFork, evCSR, evJoin;
    cudaEventCreateWithFlags(&evFork, cudaEventDisableTiming);
    cudaEventCreateWithFlags(&evCSR, cudaEventDisableTiming);
    cudaEventCreateWithFlags(&evJoin, cudaEventDisableTiming);

    // fork s2 immediately; CSR chain runs there, hidden under prep_w + GEMM1
    cudaEventRecord(evFork, 0);
    cudaStreamWaitEvent(s2, evFork, 0);

    // s2: probe + init, then CSR build
    k_prep_graph<<<NB, 256, 0, s2>>>((const int*)ei, cnt, deg);
    k_hist<<<(E + 255) / 256, 256, 0, s2>>>(cnt, deg, ei, ea, E);
    k_scan1<<<NB, 256, 0, s2>>>(cnt, fill, part, deg, dis, N);
    k_scan2<<<1, 256, 0, s2>>>(part, NB);
    k_scan3<<<NB, 256, 0, s2>>>(cnt, fill, part, rowptr, N);
    k_csr_fill<<<(E + 255) / 256, 256, 0, s2>>>(ei, ea, dis, fill, col, val, E);
    cudaEventRecord(evCSR, s2);

    // s0: weight conversion, then GEMM1 (overlapped with CSR build)
    k_prep_w<<<(IN_F * HID_F + 255) / 256, 256>>>(W1, Wmu, Wlv, w1h, w1l, w2h, w2l);
    const dim3 gg(2, (N + 127) / 128);  // 2 n-tiles x 391 m-tiles
    k_mma_gemm<IN_F, 1><<<gg, 256, SMEM_GEMM>>>(x, w1h, w1l, m1,
                                                nullptr, nullptr, nullptr, N);

    // join: gathers need both m1 and the CSR
    cudaStreamWaitEvent(0, evCSR, 0);

    // 3) agg1 = dis^2*m1[dst] + sum val*m1[src]   (CSR gather, no atomics)
    k_gather<1><<<(N + 3) / 4, 256>>>(m1, agg1, rowptr, col, val, dis, nullptr);

    // 4) agg2 = dis^2*h[dst] + sum val*h[src], h = relu(agg1+b1) on the fly
    k_gather<2><<<(N + 3) / 4, 256>>>(agg1, agg2, rowptr, col, val, dis, b1);

    // 5) [mu | logvar] = agg2 @ [Wmu | Wlv] + [bmu | blv]  (fused, N=256)
    k_mma_gemm<HID_F, 2><<<gg, 256, SMEM_GEMM>>>(agg2, w2h, w2l,
                                                 out, out + (size_t)N * LAT_F,
                                                 bmu, blv, N);

    // keep s2 joined (no-op here but keeps the graph well-formed)
    cudaEventRecord(evJoin, s2);
    cudaStreamWaitEvent(0, evJoin, 0);

    cudaEventDestroy(evFork);
    cudaEventDestroy(evCSR);
    cudaEventDestroy(evJoin);
    cudaStreamDestroy(s2);
}

// round 16
// speedup vs baseline: 1.0824x; 1.0547x over previous
#include <cuda_runtime.h>
#include <cuda_bf16.h>
#include <cstdint>

// Problem constants (fixed by the dataset)
#define NN 50000
#define EE 800000
#define IN_F 512
#define HID_F 256
#define LAT_F 128

// ---------------- scratch (static device globals; no runtime alloc) ----------
__device__ __align__(16) float g_m1[NN * HID_F];    // x @ W1
__device__ __align__(16) float g_agg1[NN * HID_F];  // layer-1 aggregate (pre-activation)
__device__ __align__(16) float g_agg2[NN * HID_F];  // layer-2 aggregate
__device__ float g_dis[NN];                         // rsqrt(deg)
__device__ float g_deg[NN];                         // weighted degree accum
__device__ int   g_cnt[NN];                         // incoming-edge count
__device__ int   g_rowptr[NN + 1];                  // CSR row pointers
__device__ int   g_fill[NN];                        // scan temp / fill cursors
__device__ int   g_part[256];                       // scan block partials
__device__ int   g_col[EE];                         // CSR: src per edge (sorted by dst)
__device__ float g_val[EE];                         // CSR: precomputed norm per edge
__device__ int   g_is64;                            // edge_index dtype flag

// Pre-transposed, bf16 hi/lo split weights: [N, K] K-major (= B col-major for mma)
__device__ __align__(16) __nv_bfloat16 g_W1T_hi[HID_F * IN_F];
__device__ __align__(16) __nv_bfloat16 g_W1T_lo[HID_F * IN_F];
__device__ __align__(16) __nv_bfloat16 g_W2T_hi[HID_F * HID_F];  // [256 (mu|lv), 256]
__device__ __align__(16) __nv_bfloat16 g_W2T_lo[HID_F * HID_F];

// ---------------- warp mma + ldmatrix (Ampere-era PTX; no arch gating) -------
__device__ __forceinline__ void mma_bf16(float* c, const uint32_t* a, const uint32_t* b) {
    asm volatile(
        "mma.sync.aligned.m16n8k16.row.col.f32.bf16.bf16.f32 "
        "{%0,%1,%2,%3}, {%4,%5,%6,%7}, {%8,%9}, {%0,%1,%2,%3};"
        : "+f"(c[0]), "+f"(c[1]), "+f"(c[2]), "+f"(c[3])
        : "r"(a[0]), "r"(a[1]), "r"(a[2]), "r"(a[3]), "r"(b[0]), "r"(b[1]));
}

#define LDSM4(r, addr)                                                          \
    asm volatile("ldmatrix.sync.aligned.m8n8.x4.shared.b16 {%0,%1,%2,%3}, [%4];" \
        : "=r"((r)[0]), "=r"((r)[1]), "=r"((r)[2]), "=r"((r)[3]) : "r"(addr))

__device__ __forceinline__ uint32_t pack_bf16x2(float x0, float x1) {
    __nv_bfloat16 h0 = __float2bfloat16(x0), h1 = __float2bfloat16(x1);
    return (uint32_t)__bfloat16_as_ushort(h0) | ((uint32_t)__bfloat16_as_ushort(h1) << 16);
}

// ================= tensor-core GEMM: C[M,256] = A[M,KTOT] @ W  ===============
// CTA tile 128(M) x 128(N); grid.x = 2 covers N=256. 8 warps = 2(M) x 4(N),
// warp tile 64x32 = 4 x 4 m16n8 fragments. Split-bf16 3-term fp32 emulation.
// Register prefetch + 2-stage SMEM double buffering + ldmatrix fragment loads
// (1 LDSM.x4 replaces 4 scalar LDS.32 per fragment; conflict-free at PADK=40).
// MODE 1: O1 = raw result (256-wide)
// MODE 2: n-half 0 -> O1 + bias1 (mu), n-half 1 -> O2 + bias2 (logvar)
#define PADK 40
#define TILE_B (128 * PADK * 2)           // 10240 bytes per tile
#define STAGE_B (4 * TILE_B)              // Ah, Al, Bh, Bl
#define SMEM_GEMM (2 * STAGE_B)           // 81920 bytes

template <int KTOT, int MODE>
__global__ __launch_bounds__(256, 1) void k_mma_gemm(
    const float* __restrict__ A,
    const __nv_bfloat16* __restrict__ Bhi, const __nv_bfloat16* __restrict__ Blo,
    float* __restrict__ O1, float* __restrict__ O2,
    const float* __restrict__ bias1, const float* __restrict__ bias2, int M)
{
    extern __shared__ __align__(16) char smraw[];

    const int t    = threadIdx.x;
    const int row0 = blockIdx.y * 128;
    const int bn   = blockIdx.x * 128;
    const int wid  = t >> 5, lane = t & 31;
    const int wm0  = (wid & 1) * 64;
    const int wn0  = (wid >> 1) * 32;
    const int g    = lane >> 2, tq = lane & 3;

    float acc[4][4][4];
    #pragma unroll
    for (int i = 0; i < 4; i++)
        #pragma unroll
        for (int j = 0; j < 4; j++)
            #pragma unroll
            for (int q = 0; q < 4; q++) acc[i][j][q] = 0.f;

    const int r_ld = t >> 1;          // 0..127
    const int k_ld = (t & 1) * 16;    // 0 or 16
    const bool a_ok = (row0 + r_ld) < M;
    const float* a_base = A + (size_t)(row0 + r_ld) * KTOT + k_ld;
    const size_t b_base = (size_t)(bn + r_ld) * KTOT + k_ld;

    // ldmatrix per-lane fragment offsets (bf16 elements)
    // A x4: mats = [rows m..m+7, k..k+7], [m+8..m+15, k..k+7], [m.., k+8], [m+8.., k+8]
    const int a_frag_off = (wm0 + (lane & 7) + ((lane >> 3) & 1) * 8) * PADK
                         + ((lane >> 4) & 1) * 8;
    // B x4: mats = [rows n..n+7] x kcols {0-7, 8-15, 16-23, 24-31} (both kk steps)
    const int b_frag_off = (wn0 + (lane & 7)) * PADK + (lane >> 3) * 8;

    float  fA[16];
    uint4  rBh[2], rBl[2];

    auto ldA = [&](int kc) {
        if (a_ok) {
            const float4* p = (const float4*)(a_base + kc);
            float4 v0 = p[0], v1 = p[1], v2 = p[2], v3 = p[3];
            fA[0]=v0.x; fA[1]=v0.y; fA[2]=v0.z; fA[3]=v0.w;
            fA[4]=v1.x; fA[5]=v1.y; fA[6]=v1.z; fA[7]=v1.w;
            fA[8]=v2.x; fA[9]=v2.y; fA[10]=v2.z; fA[11]=v2.w;
            fA[12]=v3.x; fA[13]=v3.y; fA[14]=v3.z; fA[15]=v3.w;
        } else {
            #pragma unroll
            for (int j = 0; j < 16; j++) fA[j] = 0.f;
        }
        const uint4* ph = (const uint4*)(Bhi + b_base + kc);
        const uint4* pl = (const uint4*)(Blo + b_base + kc);
        rBh[0] = ph[0]; rBh[1] = ph[1];
        rBl[0] = pl[0]; rBl[1] = pl[1];
    };

    ldA(0);  // prefetch chunk 0

    const uint32_t smem_sb = (uint32_t)__cvta_generic_to_shared(smraw);

    const int NCH = KTOT / 32;
    for (int c = 0; c < NCH; c++) {
        char* stg = smraw + (c & 1) * STAGE_B;
        __nv_bfloat16* Ah = (__nv_bfloat16*)(stg);
        __nv_bfloat16* Al = (__nv_bfloat16*)(stg + TILE_B);
        __nv_bfloat16* Bh = (__nv_bfloat16*)(stg + 2 * TILE_B);
        __nv_bfloat16* Bl = (__nv_bfloat16*)(stg + 3 * TILE_B);

        // ---- store prefetched chunk to SMEM (A: fp32 -> bf16 hi/lo split) ----
        {
            uint32_t hu[8], lu[8];
            #pragma unroll
            for (int j = 0; j < 8; j++) {
                float x0 = fA[2*j], x1 = fA[2*j+1];
                __nv_bfloat16 h0 = __float2bfloat16(x0), h1 = __float2bfloat16(x1);
                float r0 = x0 - __bfloat162float(h0);
                float r1 = x1 - __bfloat162float(h1);
                hu[j] = (uint32_t)__bfloat16_as_ushort(h0) |
                        ((uint32_t)__bfloat16_as_ushort(h1) << 16);
                lu[j] = pack_bf16x2(r0, r1);
            }
            int o = r_ld * PADK + k_ld;
            *(uint4*)&Ah[o]     = make_uint4(hu[0], hu[1], hu[2], hu[3]);
            *(uint4*)&Ah[o + 8] = make_uint4(hu[4], hu[5], hu[6], hu[7]);
            *(uint4*)&Al[o]     = make_uint4(lu[0], lu[1], lu[2], lu[3]);
            *(uint4*)&Al[o + 8] = make_uint4(lu[4], lu[5], lu[6], lu[7]);
            *(uint4*)&Bh[o]     = rBh[0];
            *(uint4*)&Bh[o + 8] = rBh[1];
            *(uint4*)&Bl[o]     = rBl[0];
            *(uint4*)&Bl[o + 8] = rBl[1];
        }
        __syncthreads();   // single sync per chunk (double-buffered stages)

        // ---- prefetch next chunk (latency overlapped with MMA below) ----
        if (c + 1 < NCH) ldA((c + 1) * 32);

        // ---- ldmatrix fragment bases for this stage ----
        const uint32_t stg_sb   = smem_sb + (uint32_t)((c & 1) * STAGE_B);
        const uint32_t ah_ldsm  = stg_sb + (uint32_t)(a_frag_off * 2);
        const uint32_t al_ldsm  = ah_ldsm + TILE_B;
        const uint32_t bh_ldsm  = stg_sb + (uint32_t)(2 * TILE_B + b_frag_off * 2);
        const uint32_t bl_ldsm  = bh_ldsm + TILE_B;

        // ---- B fragments: one x4 per nf per hi/lo covers BOTH kk steps ----
        uint32_t bhreg[4][4], blreg[4][4];
        #pragma unroll
        for (int nf = 0; nf < 4; nf++) {
            uint32_t off = (uint32_t)(nf * 8 * PADK * 2);
            LDSM4(bhreg[nf], bh_ldsm + off);
            LDSM4(blreg[nf], bl_ldsm + off);
        }

        #pragma unroll
        for (int kk = 0; kk < 32; kk += 16) {
            const int kidx = (kk >> 4) * 2;   // 0 or 2: selects b-reg pair
            #pragma unroll
            for (int mf = 0; mf < 4; mf++) {
                uint32_t off = (uint32_t)((mf * 16 * PADK + kk) * 2);
                uint32_t ah[4], al[4];
                LDSM4(ah, ah_ldsm + off);
                LDSM4(al, al_ldsm + off);
                #pragma unroll
                for (int nf = 0; nf < 4; nf++) {
                    mma_bf16(acc[mf][nf], ah, &bhreg[nf][kidx]);  // hi*hi
                    mma_bf16(acc[mf][nf], ah, &blreg[nf][kidx]);  // hi*lo
                    mma_bf16(acc[mf][nf], al, &bhreg[nf][kidx]);  // lo*hi
                }
            }
        }
    }

    // ---- epilogue: registers -> global ----
    #pragma unroll
    for (int mf = 0; mf < 4; mf++) {
        int mA = row0 + wm0 + mf * 16 + g;   // rows for c0,c1
        int mB = mA + 8;                     // rows for c2,c3
        if (MODE == 1) {
            #pragma unroll
            for (int nf = 0; nf < 4; nf++) {
                int n = bn + wn0 + nf * 8 + tq * 2;
                if (mA < M)
                    *(float2*)(O1 + (size_t)mA * 256 + n) =
                        make_float2(acc[mf][nf][0], acc[mf][nf][1]);
                if (mB < M)
                    *(float2*)(O1 + (size_t)mB * 256 + n) =
                        make_float2(acc[mf][nf][2], acc[mf][nf][3]);
            }
        } else {
            const float* bs = (bn == 0) ? bias1 : bias2;
            float* Oo = (bn == 0) ? O1 : O2;
            #pragma unroll
            for (int nf = 0; nf < 4; nf++) {
                int col = wn0 + nf * 8 + tq * 2;  // 0..127 within half
                float b0 = bs[col], b1 = bs[col + 1];
                if (mA < M)
                    *(float2*)(Oo + (size_t)mA * 128 + col) =
                        make_float2(acc[mf][nf][0] + b0, acc[mf][nf][1] + b1);
                if (mB < M)
                    *(float2*)(Oo + (size_t)mB * 128 + col) =
                        make_float2(acc[mf][nf][2] + b0, acc[mf][nf][3] + b1);
            }
        }
    }
}

// ---------------- prep A: dtype probe + cnt/deg init (feeds CSR chain) -------
__global__ void k_prep_graph(const int* __restrict__ ei_raw,
                             int* __restrict__ cnt, float* __restrict__ deg) {
    int idx = blockIdx.x * blockDim.x + threadIdx.x;
    if (idx == 0) {
        // dtype probe: node ids < 50000, so int64 => odd 32-bit words all zero
        int allzero = 1;
        #pragma unroll
        for (int i = 0; i < 8; i++)
            if (ei_raw[2 * i + 1] != 0) allzero = 0;
        g_is64 = allzero;
    }
    if (idx < NN) { cnt[idx] = 0; deg[idx] = 1.0f; }  // self-loop weight
}

// ---------------- prep B: weight transpose + bf16 split (feeds GEMMs) --------
__global__ void k_prep_w(const float* __restrict__ W1,
                         const float* __restrict__ Wmu, const float* __restrict__ Wlv,
                         __nv_bfloat16* __restrict__ w1h, __nv_bfloat16* __restrict__ w1l,
                         __nv_bfloat16* __restrict__ w2h, __nv_bfloat16* __restrict__ w2l) {
    int idx = blockIdx.x * blockDim.x + threadIdx.x;
    if (idx < IN_F * HID_F) {
        int k = idx >> 8, n = idx & 255;
        float v = W1[(size_t)k * HID_F + n];
        __nv_bfloat16 h = __float2bfloat16(v);
        __nv_bfloat16 l = __float2bfloat16(v - __bfloat162float(h));
        w1h[(size_t)n * IN_F + k] = h;
        w1l[(size_t)n * IN_F + k] = l;
    }
    if (idx < HID_F * HID_F) {
        int k = idx >> 8, n = idx & 255;
        float v = (n < 128) ? Wmu[(size_t)k * LAT_F + n] : Wlv[(size_t)k * LAT_F + (n - 128)];
        __nv_bfloat16 h = __float2bfloat16(v);
        __nv_bfloat16 l = __float2bfloat16(v - __bfloat162float(h));
        w2h[(size_t)n * HID_F + k] = h;
        w2l[(size_t)n * HID_F + k] = l;
    }
}

__device__ __forceinline__ int load_idx(const void* ei, long long pos, int is64) {
    if (is64) return (int)((const long long*)ei)[pos];
    return ((const int*)ei)[pos];
}

// ---------------- CSR construction -------------------------------------------
__global__ void k_hist(int* cnt, float* deg, const void* __restrict__ ei,
                       const float* __restrict__ w, int e_cnt) {
    int e = blockIdx.x * blockDim.x + threadIdx.x;
    if (e < e_cnt) {
        int d = load_idx(ei, (long long)e_cnt + e, g_is64);
        if ((unsigned)d < NN) {
            atomicAdd(&cnt[d], 1);
            atomicAdd(&deg[d], w[e]);
        }
    }
}

// ---- 3-phase scan over cnt[0..n): rowptr (exclusive+1) and fill cursors ----
// scan1 also computes dis = rsqrt(deg) (independent elementwise, same grid).
__device__ __forceinline__ int block_scan_incl(int x, int* ws) {
    int lane = threadIdx.x & 31, w = threadIdx.x >> 5;
    int v = x;
    #pragma unroll
    for (int o = 1; o < 32; o <<= 1) {
        int t = __shfl_up_sync(0xFFFFFFFFu, v, o);
        if (lane >= o) v += t;
    }
    if (lane == 31) ws[w] = v;
    __syncthreads();
    if (w == 0) {
        int s = (lane < 8) ? ws[lane] : 0;
        #pragma unroll
        for (int o = 1; o < 8; o <<= 1) {
            int t = __shfl_up_sync(0xFFFFFFFFu, s, o);
            if (lane >= o) s += t;
        }
        if (lane < 8) ws[lane] = s;
    }
    __syncthreads();
    return v + (w > 0 ? ws[w - 1] : 0);
}
__global__ void k_scan1(const int* __restrict__ cnt, int* __restrict__ incl,
                        int* __restrict__ part, const float* __restrict__ deg,
                        float* __restrict__ dis, int n) {
    __shared__ int ws[8];
    int i = blockIdx.x * 256 + threadIdx.x;
    if (i < n) dis[i] = rsqrtf(deg[i]);
    int x = (i < n) ? cnt[i] : 0;
    int v = block_scan_incl(x, ws);
    if (i < n) incl[i] = v;
    if (threadIdx.x == 255) part[blockIdx.x] = v;
}
__global__ void k_scan2(int* part, int nb) {  // single block, nb <= 256
    __shared__ int ws[8];
    int tid = threadIdx.x;
    int x = (tid < nb) ? part[tid] : 0;
    int v = block_scan_incl(x, ws);
    if (tid < nb) part[tid] = v - x;  // exclusive block offsets
}
__global__ void k_scan3(const int* __restrict__ cnt, int* __restrict__ incl_fill,
                        const int* __restrict__ part, int* __restrict__ rowptr, int n) {
    int i = blockIdx.x * 256 + threadIdx.x;
    if (i < n) {
        int v = incl_fill[i] + part[blockIdx.x];
        rowptr[i + 1] = v;
        incl_fill[i] = v - cnt[i];  // becomes fill cursor (exclusive)
    }
    if (i == 0) rowptr[0] = 0;
}
__global__ void k_csr_fill(const void* __restrict__ ei, const float* __restrict__ ea,
                           const float* __restrict__ dis, int* __restrict__ fill,
                           int* __restrict__ col, float* __restrict__ val, int e_cnt) {
    int e = blockIdx.x * blockDim.x + threadIdx.x;
    if (e >= e_cnt) return;
    int is64 = g_is64;
    int s = load_idx(ei, e, is64);
    int d = load_idx(ei, (long long)e_cnt + e, is64);
    if ((unsigned)s >= NN || (unsigned)d >= NN) return;
    int p = atomicAdd(&fill[d], 1);
    col[p] = s;
    val[p] = dis[s] * ea[e] * dis[d];
}

// ---------------- CSR gather: out[n,:] = d2*h(n,:) + sum val*h(col,:) --------
// PASS 1: h = identity (m = m1). PASS 2: h = relu(m + b1) (m = agg1).
// 64 threads per node (one float4 per thread), 4 nodes per 256-thread block.
template <int PASS>
__global__ __launch_bounds__(256, 4) void k_gather(
    const float* __restrict__ m, float* __restrict__ out,
    const int* __restrict__ rowptr, const int* __restrict__ col,
    const float* __restrict__ val, const float* __restrict__ dis,
    const float* __restrict__ b1)
{
    int node = blockIdx.x * 4 + (threadIdx.x >> 6);
    if (node >= NN) return;
    int part = threadIdx.x & 63;  // float4 slot within 256-wide row
    int r0 = rowptr[node], r1 = rowptr[node + 1];
    float dv = dis[node];
    float d2 = dv * dv;

    float4 b = make_float4(0.f, 0.f, 0.f, 0.f);
    if (PASS == 2) b = *(const float4*)(b1 + part * 4);

    auto act = [&](float4 a) -> float4 {
        if (PASS == 2) {
            a.x = fmaxf(a.x + b.x, 0.f); a.y = fmaxf(a.y + b.y, 0.f);
            a.z = fmaxf(a.z + b.z, 0.f); a.w = fmaxf(a.w + b.w, 0.f);
        }
        return a;
    };

    // self-loop term
    float4 s = act(*(const float4*)(m + ((size_t)node << 8) + part * 4));
    float4 acc = make_float4(s.x * d2, s.y * d2, s.z * d2, s.w * d2);

    int j = r0;
    for (; j + 4 <= r1; j += 4) {
        int   c0 = col[j], c1 = col[j+1], c2 = col[j+2], c3 = col[j+3];
        float v0 = val[j], v1 = val[j+1], v2 = val[j+2], v3 = val[j+3];
        float4 a0 = *(const float4*)(m + ((size_t)c0 << 8) + part * 4);
        float4 a1 = *(const float4*)(m + ((size_t)c1 << 8) + part * 4);
        float4 a2 = *(const float4*)(m + ((size_t)c2 << 8) + part * 4);
        float4 a3 = *(const float4*)(m + ((size_t)c3 << 8) + part * 4);
        a0 = act(a0); a1 = act(a1); a2 = act(a2); a3 = act(a3);
        acc.x += v0 * a0.x + v1 * a1.x + v2 * a2.x + v3 * a3.x;
        acc.y += v0 * a0.y + v1 * a1.y + v2 * a2.y + v3 * a3.y;
        acc.z += v0 * a0.z + v1 * a1.z + v2 * a2.z + v3 * a3.z;
        acc.w += v0 * a0.w + v1 * a1.w + v2 * a2.w + v3 * a3.w;
    }
    for (; j < r1; j++) {
        int c0 = col[j];
        float v0 = val[j];
        float4 a0 = act(*(const float4*)(m + ((size_t)c0 << 8) + part * 4));
        acc.x += v0 * a0.x; acc.y += v0 * a0.y;
        acc.z += v0 * a0.z; acc.w += v0 * a0.w;
    }
    *(float4*)(out + ((size_t)node << 8) + part * 4) = acc;
}

// ---------------- launch ------------------------------------------------------
extern "C" void kernel_launch(void* const* d_in, const int* in_sizes, int n_in,
                              void* d_out, int out_size) {
    const float* x    = (const float*)d_in[0];
    const void*  ei   = d_in[1];
    const float* ea   = (const float*)d_in[2];
    const float* W1   = (const float*)d_in[3];
    const float* b1   = (const float*)d_in[4];
    const float* Wmu  = (const float*)d_in[5];
    const float* bmu  = (const float*)d_in[6];
    const float* Wlv  = (const float*)d_in[7];
    const float* blv  = (const float*)d_in[8];
    float* out = (float*)d_out;

    float *m1, *agg1, *agg2, *dis, *deg, *val;
    int *cnt, *rowptr, *fill, *part, *col;
    __nv_bfloat16 *w1h, *w1l, *w2h, *w2l;
    cudaGetSymbolAddress((void**)&m1, g_m1);
    cudaGetSymbolAddress((void**)&agg1, g_agg1);
    cudaGetSymbolAddress((void**)&agg2, g_agg2);
    cudaGetSymbolAddress((void**)&dis, g_dis);
    cudaGetSymbolAddress((void**)&deg, g_deg);
    cudaGetSymbolAddress((void**)&cnt, g_cnt);
    cudaGetSymbolAddress((void**)&rowptr, g_rowptr);
    cudaGetSymbolAddress((void**)&fill, g_fill);
    cudaGetSymbolAddress((void**)&part, g_part);
    cudaGetSymbolAddress((void**)&col, g_col);
    cudaGetSymbolAddress((void**)&val, g_val);
    cudaGetSymbolAddress((void**)&w1h, g_W1T_hi);
    cudaGetSymbolAddress((void**)&w1l, g_W1T_lo);
    cudaGetSymbolAddress((void**)&w2h, g_W2T_hi);
    cudaGetSymbolAddress((void**)&w2l, g_W2T_lo);

    const int N = NN, E = EE;
    const int NB = (N + 255) / 256;  // 196 scan blocks

    cudaFuncSetAttribute(k_mma_gemm<IN_F, 1>,
                         cudaFuncAttributeMaxDynamicSharedMemorySize, SMEM_GEMM);
    cudaFuncSetAttribute(k_mma_gemm<HID_F, 2>,
                         cudaFuncAttributeMaxDynamicSharedMemorySize, SMEM_GEMM);

    // fork stream + events for CSR-build / GEMM1 overlap
    cudaStream_t s2;
    cudaStreamCreateWithFlags(&s2, cudaStreamNonBlocking);
    cudaEvent_t evFork, evCSR, evJoin;
    cudaEventCreateWithFlags(&evFork, cudaEventDisableTiming);
    cudaEventCreateWithFlags(&evCSR, cudaEventDisableTiming);
    cudaEventCreateWithFlags(&evJoin, cudaEventDisableTiming);

    // fork s2 immediately; CSR chain runs there, hidden under prep_w + GEMM1
    cudaEventRecord(evFork, 0);
    cudaStreamWaitEvent(s2, evFork, 0);

    // s2: probe + init, then CSR build
    k_prep_graph<<<NB, 256, 0, s2>>>((const int*)ei, cnt, deg);
    k_hist<<<(E + 255) / 256, 256, 0, s2>>>(cnt, deg, ei, ea, E);
    k_scan1<<<NB, 256, 0, s2>>>(cnt, fill, part, deg, dis, N);
    k_scan2<<<1, 256, 0, s2>>>(part, NB);
    k_scan3<<<NB, 256, 0, s2>>>(cnt, fill, part, rowptr, N);
    k_csr_fill<<<(E + 255) / 256, 256, 0, s2>>>(ei, ea, dis, fill, col, val, E);
    cudaEventRecord(evCSR, s2);

    // s0: weight conversion, then GEMM1 (overlapped with CSR build)
    k_prep_w<<<(IN_F * HID_F + 255) / 256, 256>>>(W1, Wmu, Wlv, w1h, w1l, w2h, w2l);
    const dim3 gg(2, (N + 127) / 128);  // 2 n-tiles x 391 m-tiles
    k_mma_gemm<IN_F, 1><<<gg, 256, SMEM_GEMM>>>(x, w1h, w1l, m1,
                                                nullptr, nullptr, nullptr, N);

    // join: gathers need both m1 and the CSR
    cudaStreamWaitEvent(0, evCSR, 0);

    // 3) agg1 = dis^2*m1[dst] + sum val*m1[src]   (CSR gather, no atomics)
    k_gather<1><<<(N + 3) / 4, 256>>>(m1, agg1, rowptr, col, val, dis, nullptr);

    // 4) agg2 = dis^2*h[dst] + sum val*h[src], h = relu(agg1+b1) on the fly
    k_gather<2><<<(N + 3) / 4, 256>>>(agg1, agg2, rowptr, col, val, dis, b1);

    // 5) [mu | logvar] = agg2 @ [Wmu | Wlv] + [bmu | blv]  (fused, N=256)
    k_mma_gemm<HID_F, 2><<<gg, 256, SMEM_GEMM>>>(agg2, w2h, w2l,
                                                 out, out + (size_t)N * LAT_F,
                                                 bmu, blv, N);

    // keep s2 joined (no-op here but keeps the graph well-formed)
    cudaEventRecord(evJoin, s2);
    cudaStreamWaitEvent(0, evJoin, 0);

    cudaEventDestroy(evFork);
    cudaEventDestroy(evCSR);
    cudaEventDestroy(evJoin);
    cudaStreamDestroy(s2);
}